// round 1
// baseline (speedup 1.0000x reference)
#include <cuda_runtime.h>

#define SEQ   2048
#define DIM   512
#define NH    8
#define DEPTH 64
#define NB    2
#define LOG2E 1.4426950408889634f

// ---------------- scratch (device globals; no runtime allocation) ------------
__device__ float g_qp[(size_t)NB * SEQ * DIM];
__device__ float g_kp[(size_t)NB * SEQ * DIM];
__device__ float g_vp[(size_t)NB * SEQ * DIM];
__device__ float g_attn[(size_t)NB * SEQ * DIM];
__device__ float g_qer[(size_t)NB * NH * SEQ * 1024];   // 128 MB

// ---------------- fast exp2 on the FMA pipe (avoids MUFU throughput wall) ----
__device__ __forceinline__ float fexp2(float y) {
    y = fmaxf(y, -120.0f);                 // clamp masked (-1e9-scale) values
    float r = rintf(y);
    float f = y - r;                       // f in [-0.5, 0.5]
    float p = 1.3333558146e-3f;            // ln2^5/120 ... Taylor/Horner
    p = fmaf(p, f, 9.6181291076e-3f);
    p = fmaf(p, f, 5.5504108664e-2f);
    p = fmaf(p, f, 2.4022650696e-1f);
    p = fmaf(p, f, 6.9314718056e-1f);
    p = fmaf(p, f, 1.0f);
    return p * __int_as_float(((int)r + 127) << 23);
}

// ---------------- generic NT GEMM: C = A(MxK) * B(NxK)^T + bias --------------
// Tiles 64x64, BK=16, 256 threads, 4x4 microtile, transposed smem staging so
// the inner loop is pure conflict-free LDS.128 + FMA.
__global__ void __launch_bounds__(256) gemm_nt(
    const float* __restrict__ A, int lda,
    const float* __restrict__ B, int ldb,
    const float* __restrict__ bias,
    float* __restrict__ C, int ldc, int K)
{
    __shared__ float Ats[16 * 64];
    __shared__ float Bts[16 * 64];
    const int tid = threadIdx.x;
    const int tx = tid & 15, ty = tid >> 4;
    const int m0 = blockIdx.y * 64, n0 = blockIdx.x * 64;
    const int lr = tid >> 2, lc4 = (tid & 3) * 4;
    const float* Ag = A + (size_t)(m0 + lr) * lda + lc4;
    const float* Bg = B + (size_t)(n0 + lr) * ldb + lc4;
    float acc[4][4] = {};

    for (int k0 = 0; k0 < K; k0 += 16) {
        float4 av = *(const float4*)(Ag + k0);
        float4 bv = *(const float4*)(Bg + k0);
        __syncthreads();
        Ats[(lc4 + 0) * 64 + lr] = av.x; Ats[(lc4 + 1) * 64 + lr] = av.y;
        Ats[(lc4 + 2) * 64 + lr] = av.z; Ats[(lc4 + 3) * 64 + lr] = av.w;
        Bts[(lc4 + 0) * 64 + lr] = bv.x; Bts[(lc4 + 1) * 64 + lr] = bv.y;
        Bts[(lc4 + 2) * 64 + lr] = bv.z; Bts[(lc4 + 3) * 64 + lr] = bv.w;
        __syncthreads();
        #pragma unroll
        for (int kk = 0; kk < 16; kk++) {
            float4 a4 = *(const float4*)&Ats[kk * 64 + ty * 4];
            float4 b4 = *(const float4*)&Bts[kk * 64 + tx * 4];
            float aa[4] = {a4.x, a4.y, a4.z, a4.w};
            float bb[4] = {b4.x, b4.y, b4.z, b4.w};
            #pragma unroll
            for (int i = 0; i < 4; i++)
                #pragma unroll
                for (int j = 0; j < 4; j++)
                    acc[i][j] = fmaf(aa[i], bb[j], acc[i][j]);
        }
    }
    #pragma unroll
    for (int j = 0; j < 4; j++) {
        float bj = bias ? bias[n0 + tx * 4 + j] : 0.0f;
        #pragma unroll
        for (int i = 0; i < 4; i++)
            C[(size_t)(m0 + ty * 4 + i) * ldc + n0 + tx * 4 + j] = acc[i][j] + bj;
    }
}

// ---------------- fused flash-style attention with exact skew ---------------
// grid: (SEQ/64, NH, NB), 256 threads. Q tile kept resident; K/V tiles streamed.
// P tile overlays the K tile region -> exactly 48KB static smem.
__global__ void __launch_bounds__(256) attn_kernel(
    const float* __restrict__ qp, const float* __restrict__ kp,
    const float* __restrict__ vp, const int* __restrict__ mask,
    const float* __restrict__ qer, float* __restrict__ out)
{
    __shared__ float Qts[64 * 64];   // Q transposed: [d][row]
    __shared__ float KP [64 * 64];   // K transposed: [d][col]; later P^T: [col][row]
    __shared__ float Vs [64 * 64];   // V natural:   [col][d]
    const int tid = threadIdx.x;
    const int tx = tid & 15, ty = tid >> 4;
    const int p0 = blockIdx.x * 64;
    const int h = blockIdx.y, b = blockIdx.z;

    const float* Qg = qp + ((size_t)b * SEQ) * DIM + h * DEPTH;
    const float* Kg = kp + ((size_t)b * SEQ) * DIM + h * DEPTH;
    const float* Vg = vp + ((size_t)b * SEQ) * DIM + h * DEPTH;
    const float* qerb = qer + ((size_t)(b * NH + h)) * SEQ * 1024;
    const int*   maskb = mask + (size_t)b * SEQ * SEQ;

    // stage Q tile (transposed)
    #pragma unroll
    for (int it = 0; it < 4; it++) {
        int idx = tid + it * 256;
        int lr = idx >> 4, lc4 = (idx & 15) * 4;
        float4 v = *(const float4*)(Qg + (size_t)(p0 + lr) * DIM + lc4);
        Qts[(lc4 + 0) * 64 + lr] = v.x; Qts[(lc4 + 1) * 64 + lr] = v.y;
        Qts[(lc4 + 2) * 64 + lr] = v.z; Qts[(lc4 + 3) * 64 + lr] = v.w;
    }

    float m_run[4], l_run[4], acc[4][4];
    #pragma unroll
    for (int i = 0; i < 4; i++) {
        m_run[i] = -1e30f; l_run[i] = 0.0f;
        #pragma unroll
        for (int j = 0; j < 4; j++) acc[i][j] = 0.0f;
    }

    for (int q0 = 0; q0 < SEQ; q0 += 64) {
        // issue K/V global loads before the barrier (latency hiding)
        float4 kf[4], vf[4];
        #pragma unroll
        for (int it = 0; it < 4; it++) {
            int idx = tid + it * 256;
            int lr = idx >> 4, lc4 = (idx & 15) * 4;
            kf[it] = *(const float4*)(Kg + (size_t)(q0 + lr) * DIM + lc4);
            vf[it] = *(const float4*)(Vg + (size_t)(q0 + lr) * DIM + lc4);
        }
        __syncthreads();   // prior PV readers of KP/Vs are done
        #pragma unroll
        for (int it = 0; it < 4; it++) {
            int idx = tid + it * 256;
            int lr = idx >> 4, lc4 = (idx & 15) * 4;
            KP[(lc4 + 0) * 64 + lr] = kf[it].x; KP[(lc4 + 1) * 64 + lr] = kf[it].y;
            KP[(lc4 + 2) * 64 + lr] = kf[it].z; KP[(lc4 + 3) * 64 + lr] = kf[it].w;
            *(float4*)&Vs[lr * 64 + lc4] = vf[it];
        }
        __syncthreads();

        // S = Q K^T (64x64x64)
        float sv[4][4] = {};
        #pragma unroll 16
        for (int kk = 0; kk < 64; kk++) {
            float4 a4 = *(const float4*)&Qts[kk * 64 + ty * 4];
            float4 b4 = *(const float4*)&KP[kk * 64 + tx * 4];
            float aa[4] = {a4.x, a4.y, a4.z, a4.w};
            float bb[4] = {b4.x, b4.y, b4.z, b4.w};
            #pragma unroll
            for (int i = 0; i < 4; i++)
                #pragma unroll
                for (int j = 0; j < 4; j++)
                    sv[i][j] = fmaf(aa[i], bb[j], sv[i][j]);
        }

        // relative-position skew + mask + online softmax
        #pragma unroll
        for (int i = 0; i < 4; i++) {
            int p = p0 + ty * 4 + i;
            float lm = -1e30f;
            #pragma unroll
            for (int j = 0; j < 4; j++) {
                int q = q0 + tx * 4 + j;
                float srel;
                if (q <= p) {
                    int d = p - q;
                    int jj = (d <= 1023) ? (1023 - d) : 0;
                    srel = qerb[(size_t)p * 1024 + jj];
                } else if (q == p + 1) {
                    srel = 0.0f;
                } else {
                    int m2 = q - p - 2;
                    int jj = (m2 >= 1024) ? (m2 - 1024) : 0;
                    srel = qerb[(size_t)(p + 1) * 1024 + jj];
                }
                float lg = fmaf((float)maskb[(size_t)p * SEQ + q], -1.0e9f,
                                (sv[i][j] + srel) * 0.125f);
                sv[i][j] = lg;
                lm = fmaxf(lm, lg);
            }
            #pragma unroll
            for (int o = 8; o >= 1; o >>= 1)
                lm = fmaxf(lm, __shfl_xor_sync(0xffffffffu, lm, o));
            float mnew = fmaxf(m_run[i], lm);
            float corr = fexp2((m_run[i] - mnew) * LOG2E);
            m_run[i] = mnew;
            float ls = 0.0f;
            #pragma unroll
            for (int j = 0; j < 4; j++) {
                float pv = fexp2((sv[i][j] - mnew) * LOG2E);
                sv[i][j] = pv;
                ls += pv;
            }
            #pragma unroll
            for (int o = 8; o >= 1; o >>= 1)
                ls += __shfl_xor_sync(0xffffffffu, ls, o);
            l_run[i] = l_run[i] * corr + ls;
            #pragma unroll
            for (int j = 0; j < 4; j++) acc[i][j] *= corr;
        }

        __syncthreads();  // all threads done reading KP as K
        #pragma unroll
        for (int i = 0; i < 4; i++)
            #pragma unroll
            for (int j = 0; j < 4; j++)
                KP[(tx * 4 + j) * 64 + ty * 4 + i] = sv[i][j];  // P^T
        __syncthreads();

        // O += P V (64x64x64)
        #pragma unroll 16
        for (int kk = 0; kk < 64; kk++) {
            float4 a4 = *(const float4*)&KP[kk * 64 + ty * 4];
            float4 b4 = *(const float4*)&Vs[kk * 64 + tx * 4];
            float aa[4] = {a4.x, a4.y, a4.z, a4.w};
            float bb[4] = {b4.x, b4.y, b4.z, b4.w};
            #pragma unroll
            for (int i = 0; i < 4; i++)
                #pragma unroll
                for (int j = 0; j < 4; j++)
                    acc[i][j] = fmaf(aa[i], bb[j], acc[i][j]);
        }
    }

    #pragma unroll
    for (int i = 0; i < 4; i++) {
        float inv = 1.0f / l_run[i];
        #pragma unroll
        for (int j = 0; j < 4; j++)
            out[((size_t)b * SEQ + p0 + ty * 4 + i) * DIM + h * DEPTH + tx * 4 + j]
                = acc[i][j] * inv;
    }
}

// ---------------- launch ------------------------------------------------------
extern "C" void kernel_launch(void* const* d_in, const int* in_sizes, int n_in,
                              void* d_out, int out_size) {
    const float* q    = (const float*)d_in[0];
    const float* k    = (const float*)d_in[1];
    const float* v    = (const float*)d_in[2];
    const int*   mask = (const int*)  d_in[3];
    const float* Wq_w = (const float*)d_in[4];
    const float* Wq_b = (const float*)d_in[5];
    const float* Wk_w = (const float*)d_in[6];
    const float* Wk_b = (const float*)d_in[7];
    const float* Wv_w = (const float*)d_in[8];
    const float* Wv_b = (const float*)d_in[9];
    const float* E    = (const float*)d_in[10];
    const float* Wo_w = (const float*)d_in[11];
    const float* Wo_b = (const float*)d_in[12];

    float *qp, *kp, *vp, *attn, *qer;
    cudaGetSymbolAddress((void**)&qp,   g_qp);
    cudaGetSymbolAddress((void**)&kp,   g_kp);
    cudaGetSymbolAddress((void**)&vp,   g_vp);
    cudaGetSymbolAddress((void**)&attn, g_attn);
    cudaGetSymbolAddress((void**)&qer,  g_qer);

    dim3 blk(256);
    // projections: (4096 x 512) = X (4096x512) @ W^T
    gemm_nt<<<dim3(DIM / 64, (NB * SEQ) / 64), blk>>>(q, DIM, Wq_w, DIM, Wq_b, qp, DIM, DIM);
    gemm_nt<<<dim3(DIM / 64, (NB * SEQ) / 64), blk>>>(k, DIM, Wk_w, DIM, Wk_b, kp, DIM, DIM);
    gemm_nt<<<dim3(DIM / 64, (NB * SEQ) / 64), blk>>>(v, DIM, Wv_w, DIM, Wv_b, vp, DIM, DIM);

    // QEr[b,h,p,j] = qh[b,h,p,:] . E[j, h*64:(h+1)*64]   (j in [0,1024))
    for (int z = 0; z < NB * NH; z++) {
        int b = z >> 3, h = z & 7;
        gemm_nt<<<dim3(1024 / 64, SEQ / 64), blk>>>(
            qp + ((size_t)b * SEQ) * DIM + h * DEPTH, DIM,
            E + h * DEPTH, DIM, nullptr,
            qer + (size_t)z * SEQ * 1024, 1024, DEPTH);
    }

    attn_kernel<<<dim3(SEQ / 64, NH, NB), blk>>>(qp, kp, vp, mask, qer, attn);

    // output projection -> d_out
    gemm_nt<<<dim3(DIM / 64, (NB * SEQ) / 64), blk>>>(attn, DIM, Wo_w, DIM, Wo_b,
                                                      (float*)d_out, DIM, DIM);
}

// round 2
// speedup vs baseline: 1.3602x; 1.3602x over previous
#include <cuda_runtime.h>

#define SEQ   2048
#define DIM   512
#define NH    8
#define DEPTH 64
#define NB    2
typedef unsigned long long u64;

// ---------------- scratch (device globals; no runtime allocation) ------------
__device__ float g_qp[(size_t)NB * SEQ * DIM];
__device__ float g_kp[(size_t)NB * SEQ * DIM];
__device__ float g_vp[(size_t)NB * SEQ * DIM];
__device__ float g_attn[(size_t)NB * SEQ * DIM];
__device__ float g_qer[(size_t)NB * NH * SEQ * 1024];   // 128 MB

// ---------------- packed fp32x2 helpers (FFMA2: 2x fp32 throughput) ----------
__device__ __forceinline__ u64 pk(float lo, float hi) {
    u64 r; asm("mov.b64 %0,{%1,%2};" : "=l"(r) : "f"(lo), "f"(hi)); return r;
}
__device__ __forceinline__ void fma2(u64& d, u64 a, u64 b) {
    asm("fma.rn.f32x2 %0,%1,%2,%0;" : "+l"(d) : "l"(a), "l"(b));
}
__device__ __forceinline__ float2 up(u64 v) {
    float2 r; asm("mov.b64 {%0,%1},%2;" : "=f"(r.x), "=f"(r.y) : "l"(v)); return r;
}

// ---------------- fast exp2 on the FMA pipe (no MUFU, no F2I) ----------------
// caller guarantees y >= -80 (clamped); uses magic-number round.
__device__ __forceinline__ float fexp2(float y) {
    float t = y + 12582912.0f;           // 1.5 * 2^23 : round-to-nearest int
    float r = t - 12582912.0f;
    float f = y - r;                     // f in [-0.5, 0.5]
    float p = 1.3333558146e-3f;
    p = fmaf(p, f, 9.6181291076e-3f);
    p = fmaf(p, f, 5.5504108664e-2f);
    p = fmaf(p, f, 2.4022650696e-1f);
    p = fmaf(p, f, 6.9314718056e-1f);
    p = fmaf(p, f, 1.0f);
    int R = __float_as_int(t) - 0x4B400000;         // = (int)r
    return p * __int_as_float((R + 127) << 23);
}

// ---------------- 128x128 NT GEMM body, 8x8 microtile, FFMA2 -----------------
// C(MxN) = A(MxK) * B(NxK)^T + bias.  256 threads. BK=16.
__device__ __forceinline__ void gemm128_body(
    const float* __restrict__ A, int lda,
    const float* __restrict__ B, int ldb,
    const float* __restrict__ bias,
    float* __restrict__ C, int ldc, int K,
    float* As, float* Bs)
{
    const int tid = threadIdx.x;
    const int tx = tid & 15, ty = tid >> 4;
    const int m0 = blockIdx.y * 128, n0 = blockIdx.x * 128;
    const int lrow = tid >> 2, lc4 = (tid & 3) * 4;
    const float* Ag = A + (size_t)(m0 + lrow) * lda + lc4;
    const float* Bg = B + (size_t)(n0 + lrow) * ldb + lc4;

    u64 acc[8][4];
    #pragma unroll
    for (int i = 0; i < 8; i++)
        #pragma unroll
        for (int j = 0; j < 4; j++) acc[i][j] = 0ull;

    for (int k0 = 0; k0 < K; k0 += 16) {
        float4 a0 = *(const float4*)(Ag + k0);
        float4 a1 = *(const float4*)(Ag + (size_t)64 * lda + k0);
        float4 b0 = *(const float4*)(Bg + k0);
        float4 b1 = *(const float4*)(Bg + (size_t)64 * ldb + k0);
        __syncthreads();
        As[(lc4 + 0) * 128 + lrow] = a0.x; As[(lc4 + 1) * 128 + lrow] = a0.y;
        As[(lc4 + 2) * 128 + lrow] = a0.z; As[(lc4 + 3) * 128 + lrow] = a0.w;
        As[(lc4 + 0) * 128 + lrow + 64] = a1.x; As[(lc4 + 1) * 128 + lrow + 64] = a1.y;
        As[(lc4 + 2) * 128 + lrow + 64] = a1.z; As[(lc4 + 3) * 128 + lrow + 64] = a1.w;
        Bs[(lc4 + 0) * 128 + lrow] = b0.x; Bs[(lc4 + 1) * 128 + lrow] = b0.y;
        Bs[(lc4 + 2) * 128 + lrow] = b0.z; Bs[(lc4 + 3) * 128 + lrow] = b0.w;
        Bs[(lc4 + 0) * 128 + lrow + 64] = b1.x; Bs[(lc4 + 1) * 128 + lrow + 64] = b1.y;
        Bs[(lc4 + 2) * 128 + lrow + 64] = b1.z; Bs[(lc4 + 3) * 128 + lrow + 64] = b1.w;
        __syncthreads();
        #pragma unroll
        for (int kk = 0; kk < 16; kk++) {
            float4 x0 = *(const float4*)&As[kk * 128 + ty * 8];
            float4 x1 = *(const float4*)&As[kk * 128 + ty * 8 + 4];
            float4 y0 = *(const float4*)&Bs[kk * 128 + tx * 8];
            float4 y1 = *(const float4*)&Bs[kk * 128 + tx * 8 + 4];
            u64 bp0 = pk(y0.x, y0.y), bp1 = pk(y0.z, y0.w);
            u64 bp2 = pk(y1.x, y1.y), bp3 = pk(y1.z, y1.w);
            float av[8] = {x0.x, x0.y, x0.z, x0.w, x1.x, x1.y, x1.z, x1.w};
            #pragma unroll
            for (int i = 0; i < 8; i++) {
                u64 as = pk(av[i], av[i]);
                fma2(acc[i][0], as, bp0);
                fma2(acc[i][1], as, bp1);
                fma2(acc[i][2], as, bp2);
                fma2(acc[i][3], as, bp3);
            }
        }
    }
    float bj[8];
    #pragma unroll
    for (int j = 0; j < 8; j++) bj[j] = bias ? bias[n0 + tx * 8 + j] : 0.0f;
    #pragma unroll
    for (int i = 0; i < 8; i++) {
        float2 c0 = up(acc[i][0]), c1 = up(acc[i][1]);
        float2 c2 = up(acc[i][2]), c3 = up(acc[i][3]);
        float4 o0 = {c0.x + bj[0], c0.y + bj[1], c1.x + bj[2], c1.y + bj[3]};
        float4 o1 = {c2.x + bj[4], c2.y + bj[5], c3.x + bj[6], c3.y + bj[7]};
        float* Cr = C + (size_t)(m0 + ty * 8 + i) * ldc + n0 + tx * 8;
        *(float4*)Cr = o0;
        *(float4*)(Cr + 4) = o1;
    }
}

struct Batch3 {
    const float* A[3]; const float* B[3]; const float* bias[3]; float* C[3];
};

// projections (grid.z selects q/k/v) and the final output projection
__global__ void __launch_bounds__(256) gemm128_batched(
    Batch3 bt, int lda, int ldb, int ldc, int K)
{
    __shared__ float As[16 * 128];
    __shared__ float Bs[16 * 128];
    int z = blockIdx.z;
    gemm128_body(bt.A[z], lda, bt.B[z], ldb, bt.bias[z], bt.C[z], ldc, K, As, Bs);
}

// QEr[b,h][p][j] = qh[b,h,p,:] . E[j, h*64:(h+1)*64]   one launch, z = b*8+h
__global__ void __launch_bounds__(256) gemm128_qer(
    const float* __restrict__ qp, const float* __restrict__ E,
    float* __restrict__ qer)
{
    __shared__ float As[16 * 128];
    __shared__ float Bs[16 * 128];
    int z = blockIdx.z, b = z >> 3, h = z & 7;
    gemm128_body(qp + ((size_t)b * SEQ) * DIM + h * DEPTH, DIM,
                 E + h * DEPTH, DIM, nullptr,
                 qer + (size_t)z * SEQ * 1024, 1024, DEPTH, As, Bs);
}

// ---------------- fused flash attention, FFMA2, max-free softmax -------------
#define C1   0.18033688011112043f     /* 0.125 * log2(e) */
#define MBIG -1.8033688011112043e8f   /* -1e9 * C1 */

__global__ void __launch_bounds__(256) attn_kernel(
    const float* __restrict__ qp, const float* __restrict__ kp,
    const float* __restrict__ vp, const int* __restrict__ mask,
    const float* __restrict__ qer, float* __restrict__ out)
{
    __shared__ float Qts[64 * 64];   // Q transposed: [d][row]
    __shared__ float KP [64 * 64];   // K transposed: [d][col]; later P^T: [q][p]
    __shared__ float Vs [64 * 64];   // V natural:   [q][d]
    const int tid = threadIdx.x;
    const int tx = tid & 15, ty = tid >> 4;
    const int p0 = blockIdx.x * 64;
    const int h = blockIdx.y, b = blockIdx.z;

    const float* Qg = qp + ((size_t)b * SEQ) * DIM + h * DEPTH;
    const float* Kg = kp + ((size_t)b * SEQ) * DIM + h * DEPTH;
    const float* Vg = vp + ((size_t)b * SEQ) * DIM + h * DEPTH;
    const float* qerb = qer + ((size_t)(b * NH + h)) * SEQ * 1024;
    const int*   maskb = mask + (size_t)b * SEQ * SEQ;

    // stage Q tile (transposed)
    #pragma unroll
    for (int it = 0; it < 4; it++) {
        int idx = tid + it * 256;
        int lr = idx >> 4, lc4 = (idx & 15) * 4;
        float4 v = *(const float4*)(Qg + (size_t)(p0 + lr) * DIM + lc4);
        Qts[(lc4 + 0) * 64 + lr] = v.x; Qts[(lc4 + 1) * 64 + lr] = v.y;
        Qts[(lc4 + 2) * 64 + lr] = v.z; Qts[(lc4 + 3) * 64 + lr] = v.w;
    }

    u64 acc[4][2];
    float lsum[4];
    #pragma unroll
    for (int i = 0; i < 4; i++) {
        lsum[i] = 0.0f;
        acc[i][0] = 0ull; acc[i][1] = 0ull;
    }

    for (int q0 = 0; q0 < SEQ; q0 += 64) {
        // ---- issue all global loads for this tile up front -------------
        float4 kf[4], vf[4];
        #pragma unroll
        for (int it = 0; it < 4; it++) {
            int idx = tid + it * 256;
            int lr = idx >> 4, lc4 = (idx & 15) * 4;
            kf[it] = *(const float4*)(Kg + (size_t)(q0 + lr) * DIM + lc4);
            vf[it] = *(const float4*)(Vg + (size_t)(q0 + lr) * DIM + lc4);
        }
        float srl[4][4], mc[4][4];
        #pragma unroll
        for (int i = 0; i < 4; i++) {
            int p = p0 + ty * 4 + i;
            const float* qrow  = qerb + (size_t)p * 1024;
            const float* qrow1 = qerb + (size_t)(p + 1) * 1024;
            int4 mm = *(const int4*)(maskb + (size_t)p * SEQ + q0 + tx * 4);
            int mv[4] = {mm.x, mm.y, mm.z, mm.w};
            #pragma unroll
            for (int j = 0; j < 4; j++) {
                int q = q0 + tx * 4 + j;
                float s;
                if (q <= p) {
                    int d = p - q;
                    s = qrow[(d <= 1023) ? (1023 - d) : 0];
                } else if (q == p + 1) {
                    s = 0.0f;
                } else {
                    int m2 = q - p - 2;
                    s = qrow1[(m2 >= 1024) ? (m2 - 1024) : 0];
                }
                srl[i][j] = s;
                mc[i][j] = mv[j] ? MBIG : 0.0f;
            }
        }
        __syncthreads();   // prior PV readers of KP/Vs are done
        #pragma unroll
        for (int it = 0; it < 4; it++) {
            int idx = tid + it * 256;
            int lr = idx >> 4, lc4 = (idx & 15) * 4;
            KP[(lc4 + 0) * 64 + lr] = kf[it].x; KP[(lc4 + 1) * 64 + lr] = kf[it].y;
            KP[(lc4 + 2) * 64 + lr] = kf[it].z; KP[(lc4 + 3) * 64 + lr] = kf[it].w;
            *(float4*)&Vs[lr * 64 + lc4] = vf[it];
        }
        __syncthreads();

        // ---- S = Q K^T (64x64x64) via FFMA2 -----------------------------
        u64 sv[4][2];
        #pragma unroll
        for (int i = 0; i < 4; i++) { sv[i][0] = 0ull; sv[i][1] = 0ull; }
        #pragma unroll 16
        for (int kk = 0; kk < 64; kk++) {
            float4 a4 = *(const float4*)&Qts[kk * 64 + ty * 4];
            float4 b4 = *(const float4*)&KP[kk * 64 + tx * 4];
            u64 bp0 = pk(b4.x, b4.y), bp1 = pk(b4.z, b4.w);
            float av[4] = {a4.x, a4.y, a4.z, a4.w};
            #pragma unroll
            for (int i = 0; i < 4; i++) {
                u64 as = pk(av[i], av[i]);
                fma2(sv[i][0], as, bp0);
                fma2(sv[i][1], as, bp1);
            }
        }

        // ---- skew + mask + exp (max-free), local sum only ---------------
        float pvv[4][4];
        #pragma unroll
        for (int i = 0; i < 4; i++) {
            float2 s0 = up(sv[i][0]), s1 = up(sv[i][1]);
            float s[4] = {s0.x, s0.y, s1.x, s1.y};
            #pragma unroll
            for (int j = 0; j < 4; j++) {
                float y = fmaf(s[j] + srl[i][j], C1, mc[i][j]);
                y = fmaxf(y, -80.0f);
                float e = fexp2(y);
                pvv[i][j] = e;
                lsum[i] += e;
            }
        }

        __syncthreads();  // all threads done reading KP as K
        #pragma unroll
        for (int i = 0; i < 4; i++)
            #pragma unroll
            for (int j = 0; j < 4; j++)
                KP[(tx * 4 + j) * 64 + ty * 4 + i] = pvv[i][j];  // P^T
        __syncthreads();

        // ---- O += P V (64x64x64) via FFMA2 -------------------------------
        #pragma unroll 16
        for (int kk = 0; kk < 64; kk++) {
            float4 a4 = *(const float4*)&KP[kk * 64 + ty * 4];
            float4 b4 = *(const float4*)&Vs[kk * 64 + tx * 4];
            u64 bp0 = pk(b4.x, b4.y), bp1 = pk(b4.z, b4.w);
            float av[4] = {a4.x, a4.y, a4.z, a4.w};
            #pragma unroll
            for (int i = 0; i < 4; i++) {
                u64 as = pk(av[i], av[i]);
                fma2(acc[i][0], as, bp0);
                fma2(acc[i][1], as, bp1);
            }
        }
    }

    // ---- final row-sum reduction (once) and store ------------------------
    #pragma unroll
    for (int i = 0; i < 4; i++) {
        #pragma unroll
        for (int o = 8; o >= 1; o >>= 1)
            lsum[i] += __shfl_xor_sync(0xffffffffu, lsum[i], o);
        float inv = 1.0f / lsum[i];
        float2 c0 = up(acc[i][0]), c1 = up(acc[i][1]);
        float4 o0 = {c0.x * inv, c0.y * inv, c1.x * inv, c1.y * inv};
        *(float4*)&out[((size_t)b * SEQ + p0 + ty * 4 + i) * DIM + h * DEPTH + tx * 4] = o0;
    }
}

// ---------------- launch ------------------------------------------------------
extern "C" void kernel_launch(void* const* d_in, const int* in_sizes, int n_in,
                              void* d_out, int out_size) {
    const float* q    = (const float*)d_in[0];
    const float* k    = (const float*)d_in[1];
    const float* v    = (const float*)d_in[2];
    const int*   mask = (const int*)  d_in[3];
    const float* Wq_w = (const float*)d_in[4];
    const float* Wq_b = (const float*)d_in[5];
    const float* Wk_w = (const float*)d_in[6];
    const float* Wk_b = (const float*)d_in[7];
    const float* Wv_w = (const float*)d_in[8];
    const float* Wv_b = (const float*)d_in[9];
    const float* E    = (const float*)d_in[10];
    const float* Wo_w = (const float*)d_in[11];
    const float* Wo_b = (const float*)d_in[12];

    float *qp, *kp, *vp, *attn, *qer;
    cudaGetSymbolAddress((void**)&qp,   g_qp);
    cudaGetSymbolAddress((void**)&kp,   g_kp);
    cudaGetSymbolAddress((void**)&vp,   g_vp);
    cudaGetSymbolAddress((void**)&attn, g_attn);
    cudaGetSymbolAddress((void**)&qer,  g_qer);

    dim3 blk(256);

    // 1) q/k/v projections in one batched launch: (4096x512) x (512x512)^T
    Batch3 pb;
    pb.A[0] = q;  pb.B[0] = Wq_w; pb.bias[0] = Wq_b; pb.C[0] = qp;
    pb.A[1] = k;  pb.B[1] = Wk_w; pb.bias[1] = Wk_b; pb.C[1] = kp;
    pb.A[2] = v;  pb.B[2] = Wv_w; pb.bias[2] = Wv_b; pb.C[2] = vp;
    gemm128_batched<<<dim3(DIM / 128, (NB * SEQ) / 128, 3), blk>>>(pb, DIM, DIM, DIM, DIM);

    // 2) all 16 QEr GEMMs in one launch (M=2048, N=1024, K=64 each)
    gemm128_qer<<<dim3(1024 / 128, SEQ / 128, NB * NH), blk>>>(qp, E, qer);

    // 3) fused attention
    attn_kernel<<<dim3(SEQ / 64, NH, NB), blk>>>(qp, kp, vp, mask, qer, attn);

    // 4) output projection -> d_out
    Batch3 ob;
    ob.A[0] = attn; ob.B[0] = Wo_w; ob.bias[0] = Wo_b; ob.C[0] = (float*)d_out;
    gemm128_batched<<<dim3(DIM / 128, (NB * SEQ) / 128, 1), blk>>>(ob, DIM, DIM, DIM, DIM);
}

// round 3
// speedup vs baseline: 1.3605x; 1.0002x over previous
#include <cuda_runtime.h>

#define SEQ   2048
#define DIM   512
#define NH    8
#define DEPTH 64
#define NB    2
typedef unsigned long long u64;

// ---------------- scratch (device globals; no runtime allocation) ------------
__device__ float g_qp[(size_t)NB * SEQ * DIM];
__device__ float g_kp[(size_t)NB * SEQ * DIM];
__device__ float g_vp[(size_t)NB * SEQ * DIM];
__device__ float g_attn[(size_t)NB * SEQ * DIM];
__device__ float g_qer[(size_t)NB * NH * SEQ * 1024];   // 128 MB

// ---------------- packed fp32x2 helpers (FFMA2: 2x fp32 throughput) ----------
__device__ __forceinline__ u64 pk(float lo, float hi) {
    u64 r; asm("mov.b64 %0,{%1,%2};" : "=l"(r) : "f"(lo), "f"(hi)); return r;
}
__device__ __forceinline__ void fma2(u64& d, u64 a, u64 b) {
    asm("fma.rn.f32x2 %0,%1,%2,%0;" : "+l"(d) : "l"(a), "l"(b));
}
__device__ __forceinline__ float2 up(u64 v) {
    float2 r; asm("mov.b64 {%0,%1},%2;" : "=f"(r.x), "=f"(r.y) : "l"(v)); return r;
}

// ---------------- fast exp2 on the FMA pipe (no MUFU, no F2I) ----------------
// caller guarantees y >= -80 (clamped); uses magic-number round.
__device__ __forceinline__ float fexp2(float y) {
    float t = y + 12582912.0f;           // 1.5 * 2^23 : round-to-nearest int
    float r = t - 12582912.0f;
    float f = y - r;                     // f in [-0.5, 0.5]
    float p = 1.3333558146e-3f;
    p = fmaf(p, f, 9.6181291076e-3f);
    p = fmaf(p, f, 5.5504108664e-2f);
    p = fmaf(p, f, 2.4022650696e-1f);
    p = fmaf(p, f, 6.9314718056e-1f);
    p = fmaf(p, f, 1.0f);
    int R = __float_as_int(t) - 0x4B400000;         // = (int)r
    return p * __int_as_float((R + 127) << 23);
}

// ---------------- 128x128 NT GEMM body, 8x8 microtile, FFMA2 -----------------
// C(MxN) = A(MxK) * B(NxK)^T + bias.  256 threads. BK=16.
__device__ __forceinline__ void gemm128_body(
    const float* __restrict__ A, int lda,
    const float* __restrict__ B, int ldb,
    const float* __restrict__ bias,
    float* __restrict__ C, int ldc, int K,
    float* As, float* Bs)
{
    const int tid = threadIdx.x;
    const int tx = tid & 15, ty = tid >> 4;
    const int m0 = blockIdx.y * 128, n0 = blockIdx.x * 128;
    const int lrow = tid >> 2, lc4 = (tid & 3) * 4;
    const float* Ag = A + (size_t)(m0 + lrow) * lda + lc4;
    const float* Bg = B + (size_t)(n0 + lrow) * ldb + lc4;

    u64 acc[8][4];
    #pragma unroll
    for (int i = 0; i < 8; i++)
        #pragma unroll
        for (int j = 0; j < 4; j++) acc[i][j] = 0ull;

    for (int k0 = 0; k0 < K; k0 += 16) {
        float4 a0 = *(const float4*)(Ag + k0);
        float4 a1 = *(const float4*)(Ag + (size_t)64 * lda + k0);
        float4 b0 = *(const float4*)(Bg + k0);
        float4 b1 = *(const float4*)(Bg + (size_t)64 * ldb + k0);
        __syncthreads();
        As[(lc4 + 0) * 128 + lrow] = a0.x; As[(lc4 + 1) * 128 + lrow] = a0.y;
        As[(lc4 + 2) * 128 + lrow] = a0.z; As[(lc4 + 3) * 128 + lrow] = a0.w;
        As[(lc4 + 0) * 128 + lrow + 64] = a1.x; As[(lc4 + 1) * 128 + lrow + 64] = a1.y;
        As[(lc4 + 2) * 128 + lrow + 64] = a1.z; As[(lc4 + 3) * 128 + lrow + 64] = a1.w;
        Bs[(lc4 + 0) * 128 + lrow] = b0.x; Bs[(lc4 + 1) * 128 + lrow] = b0.y;
        Bs[(lc4 + 2) * 128 + lrow] = b0.z; Bs[(lc4 + 3) * 128 + lrow] = b0.w;
        Bs[(lc4 + 0) * 128 + lrow + 64] = b1.x; Bs[(lc4 + 1) * 128 + lrow + 64] = b1.y;
        Bs[(lc4 + 2) * 128 + lrow + 64] = b1.z; Bs[(lc4 + 3) * 128 + lrow + 64] = b1.w;
        __syncthreads();
        #pragma unroll
        for (int kk = 0; kk < 16; kk++) {
            float4 x0 = *(const float4*)&As[kk * 128 + ty * 8];
            float4 x1 = *(const float4*)&As[kk * 128 + ty * 8 + 4];
            float4 y0 = *(const float4*)&Bs[kk * 128 + tx * 8];
            float4 y1 = *(const float4*)&Bs[kk * 128 + tx * 8 + 4];
            u64 bp0 = pk(y0.x, y0.y), bp1 = pk(y0.z, y0.w);
            u64 bp2 = pk(y1.x, y1.y), bp3 = pk(y1.z, y1.w);
            float av[8] = {x0.x, x0.y, x0.z, x0.w, x1.x, x1.y, x1.z, x1.w};
            #pragma unroll
            for (int i = 0; i < 8; i++) {
                u64 as = pk(av[i], av[i]);
                fma2(acc[i][0], as, bp0);
                fma2(acc[i][1], as, bp1);
                fma2(acc[i][2], as, bp2);
                fma2(acc[i][3], as, bp3);
            }
        }
    }
    float bj[8];
    #pragma unroll
    for (int j = 0; j < 8; j++) bj[j] = bias ? bias[n0 + tx * 8 + j] : 0.0f;
    #pragma unroll
    for (int i = 0; i < 8; i++) {
        float2 c0 = up(acc[i][0]), c1 = up(acc[i][1]);
        float2 c2 = up(acc[i][2]), c3 = up(acc[i][3]);
        float4 o0 = {c0.x + bj[0], c0.y + bj[1], c1.x + bj[2], c1.y + bj[3]};
        float4 o1 = {c2.x + bj[4], c2.y + bj[5], c3.x + bj[6], c3.y + bj[7]};
        float* Cr = C + (size_t)(m0 + ty * 8 + i) * ldc + n0 + tx * 8;
        *(float4*)Cr = o0;
        *(float4*)(Cr + 4) = o1;
    }
}

struct Batch3 {
    const float* A[3]; const float* B[3]; const float* bias[3]; float* C[3];
};

// projections (grid.z selects q/k/v) and the final output projection
__global__ void __launch_bounds__(256) gemm128_batched(
    Batch3 bt, int lda, int ldb, int ldc, int K)
{
    __shared__ float As[16 * 128];
    __shared__ float Bs[16 * 128];
    int z = blockIdx.z;
    gemm128_body(bt.A[z], lda, bt.B[z], ldb, bt.bias[z], bt.C[z], ldc, K, As, Bs);
}

// QEr[b,h][p][j] = qh[b,h,p,:] . E[j, h*64:(h+1)*64]   one launch, z = b*8+h
__global__ void __launch_bounds__(256) gemm128_qer(
    const float* __restrict__ qp, const float* __restrict__ E,
    float* __restrict__ qer)
{
    __shared__ float As[16 * 128];
    __shared__ float Bs[16 * 128];
    int z = blockIdx.z, b = z >> 3, h = z & 7;
    gemm128_body(qp + ((size_t)b * SEQ) * DIM + h * DEPTH, DIM,
                 E + h * DEPTH, DIM, nullptr,
                 qer + (size_t)z * SEQ * 1024, 1024, DEPTH, As, Bs);
}

// ---------------- fused flash attention, FFMA2, max-free softmax -------------
#define C1   0.18033688011112043f     /* 0.125 * log2(e) */
#define MBIG -1.8033688011112043e8f   /* -1e9 * C1 */

__global__ void __launch_bounds__(256) attn_kernel(
    const float* __restrict__ qp, const float* __restrict__ kp,
    const float* __restrict__ vp, const int* __restrict__ mask,
    const float* __restrict__ qer, float* __restrict__ out)
{
    __shared__ float Qts[64 * 64];   // Q transposed: [d][row]
    __shared__ float KP [64 * 64];   // K transposed: [d][col]; later P^T: [q][p]
    __shared__ float Vs [64 * 64];   // V natural:   [q][d]
    const int tid = threadIdx.x;
    const int tx = tid & 15, ty = tid >> 4;
    const int p0 = blockIdx.x * 64;
    const int h = blockIdx.y, b = blockIdx.z;

    const float* Qg = qp + ((size_t)b * SEQ) * DIM + h * DEPTH;
    const float* Kg = kp + ((size_t)b * SEQ) * DIM + h * DEPTH;
    const float* Vg = vp + ((size_t)b * SEQ) * DIM + h * DEPTH;
    const float* qerb = qer + ((size_t)(b * NH + h)) * SEQ * 1024;
    const int*   maskb = mask + (size_t)b * SEQ * SEQ;

    // stage Q tile (transposed)
    #pragma unroll
    for (int it = 0; it < 4; it++) {
        int idx = tid + it * 256;
        int lr = idx >> 4, lc4 = (idx & 15) * 4;
        float4 v = *(const float4*)(Qg + (size_t)(p0 + lr) * DIM + lc4);
        Qts[(lc4 + 0) * 64 + lr] = v.x; Qts[(lc4 + 1) * 64 + lr] = v.y;
        Qts[(lc4 + 2) * 64 + lr] = v.z; Qts[(lc4 + 3) * 64 + lr] = v.w;
    }

    u64 acc[4][2];
    float lsum[4];
    #pragma unroll
    for (int i = 0; i < 4; i++) {
        lsum[i] = 0.0f;
        acc[i][0] = 0ull; acc[i][1] = 0ull;
    }

    for (int q0 = 0; q0 < SEQ; q0 += 64) {
        // ---- issue all global loads for this tile up front -------------
        float4 kf[4], vf[4];
        #pragma unroll
        for (int it = 0; it < 4; it++) {
            int idx = tid + it * 256;
            int lr = idx >> 4, lc4 = (idx & 15) * 4;
            kf[it] = *(const float4*)(Kg + (size_t)(q0 + lr) * DIM + lc4);
            vf[it] = *(const float4*)(Vg + (size_t)(q0 + lr) * DIM + lc4);
        }
        float srl[4][4], mc[4][4];
        #pragma unroll
        for (int i = 0; i < 4; i++) {
            int p = p0 + ty * 4 + i;
            const float* qrow  = qerb + (size_t)p * 1024;
            const float* qrow1 = qerb + (size_t)(p + 1) * 1024;
            int4 mm = *(const int4*)(maskb + (size_t)p * SEQ + q0 + tx * 4);
            int mv[4] = {mm.x, mm.y, mm.z, mm.w};
            #pragma unroll
            for (int j = 0; j < 4; j++) {
                int q = q0 + tx * 4 + j;
                float s;
                if (q <= p) {
                    int d = p - q;
                    s = qrow[(d <= 1023) ? (1023 - d) : 0];
                } else if (q == p + 1) {
                    s = 0.0f;
                } else {
                    int m2 = q - p - 2;
                    s = qrow1[(m2 >= 1024) ? (m2 - 1024) : 0];
                }
                srl[i][j] = s;
                mc[i][j] = mv[j] ? MBIG : 0.0f;
            }
        }
        __syncthreads();   // prior PV readers of KP/Vs are done
        #pragma unroll
        for (int it = 0; it < 4; it++) {
            int idx = tid + it * 256;
            int lr = idx >> 4, lc4 = (idx & 15) * 4;
            KP[(lc4 + 0) * 64 + lr] = kf[it].x; KP[(lc4 + 1) * 64 + lr] = kf[it].y;
            KP[(lc4 + 2) * 64 + lr] = kf[it].z; KP[(lc4 + 3) * 64 + lr] = kf[it].w;
            *(float4*)&Vs[lr * 64 + lc4] = vf[it];
        }
        __syncthreads();

        // ---- S = Q K^T (64x64x64) via FFMA2 -----------------------------
        u64 sv[4][2];
        #pragma unroll
        for (int i = 0; i < 4; i++) { sv[i][0] = 0ull; sv[i][1] = 0ull; }
        #pragma unroll 16
        for (int kk = 0; kk < 64; kk++) {
            float4 a4 = *(const float4*)&Qts[kk * 64 + ty * 4];
            float4 b4 = *(const float4*)&KP[kk * 64 + tx * 4];
            u64 bp0 = pk(b4.x, b4.y), bp1 = pk(b4.z, b4.w);
            float av[4] = {a4.x, a4.y, a4.z, a4.w};
            #pragma unroll
            for (int i = 0; i < 4; i++) {
                u64 as = pk(av[i], av[i]);
                fma2(sv[i][0], as, bp0);
                fma2(sv[i][1], as, bp1);
            }
        }

        // ---- skew + mask + exp (max-free), local sum only ---------------
        float pvv[4][4];
        #pragma unroll
        for (int i = 0; i < 4; i++) {
            float2 s0 = up(sv[i][0]), s1 = up(sv[i][1]);
            float s[4] = {s0.x, s0.y, s1.x, s1.y};
            #pragma unroll
            for (int j = 0; j < 4; j++) {
                float y = fmaf(s[j] + srl[i][j], C1, mc[i][j]);
                y = fmaxf(y, -80.0f);
                float e = fexp2(y);
                pvv[i][j] = e;
                lsum[i] += e;
            }
        }

        __syncthreads();  // all threads done reading KP as K
        #pragma unroll
        for (int i = 0; i < 4; i++)
            #pragma unroll
            for (int j = 0; j < 4; j++)
                KP[(tx * 4 + j) * 64 + ty * 4 + i] = pvv[i][j];  // P^T
        __syncthreads();

        // ---- O += P V (64x64x64) via FFMA2 -------------------------------
        #pragma unroll 16
        for (int kk = 0; kk < 64; kk++) {
            float4 a4 = *(const float4*)&KP[kk * 64 + ty * 4];
            float4 b4 = *(const float4*)&Vs[kk * 64 + tx * 4];
            u64 bp0 = pk(b4.x, b4.y), bp1 = pk(b4.z, b4.w);
            float av[4] = {a4.x, a4.y, a4.z, a4.w};
            #pragma unroll
            for (int i = 0; i < 4; i++) {
                u64 as = pk(av[i], av[i]);
                fma2(acc[i][0], as, bp0);
                fma2(acc[i][1], as, bp1);
            }
        }
    }

    // ---- final row-sum reduction (once) and store ------------------------
    #pragma unroll
    for (int i = 0; i < 4; i++) {
        #pragma unroll
        for (int o = 8; o >= 1; o >>= 1)
            lsum[i] += __shfl_xor_sync(0xffffffffu, lsum[i], o);
        float inv = 1.0f / lsum[i];
        float2 c0 = up(acc[i][0]), c1 = up(acc[i][1]);
        float4 o0 = {c0.x * inv, c0.y * inv, c1.x * inv, c1.y * inv};
        *(float4*)&out[((size_t)b * SEQ + p0 + ty * 4 + i) * DIM + h * DEPTH + tx * 4] = o0;
    }
}

// ---------------- launch ------------------------------------------------------
extern "C" void kernel_launch(void* const* d_in, const int* in_sizes, int n_in,
                              void* d_out, int out_size) {
    const float* q    = (const float*)d_in[0];
    const float* k    = (const float*)d_in[1];
    const float* v    = (const float*)d_in[2];
    const int*   mask = (const int*)  d_in[3];
    const float* Wq_w = (const float*)d_in[4];
    const float* Wq_b = (const float*)d_in[5];
    const float* Wk_w = (const float*)d_in[6];
    const float* Wk_b = (const float*)d_in[7];
    const float* Wv_w = (const float*)d_in[8];
    const float* Wv_b = (const float*)d_in[9];
    const float* E    = (const float*)d_in[10];
    const float* Wo_w = (const float*)d_in[11];
    const float* Wo_b = (const float*)d_in[12];

    float *qp, *kp, *vp, *attn, *qer;
    cudaGetSymbolAddress((void**)&qp,   g_qp);
    cudaGetSymbolAddress((void**)&kp,   g_kp);
    cudaGetSymbolAddress((void**)&vp,   g_vp);
    cudaGetSymbolAddress((void**)&attn, g_attn);
    cudaGetSymbolAddress((void**)&qer,  g_qer);

    dim3 blk(256);

    // 1) q/k/v projections in one batched launch: (4096x512) x (512x512)^T
    Batch3 pb;
    pb.A[0] = q;  pb.B[0] = Wq_w; pb.bias[0] = Wq_b; pb.C[0] = qp;
    pb.A[1] = k;  pb.B[1] = Wk_w; pb.bias[1] = Wk_b; pb.C[1] = kp;
    pb.A[2] = v;  pb.B[2] = Wv_w; pb.bias[2] = Wv_b; pb.C[2] = vp;
    gemm128_batched<<<dim3(DIM / 128, (NB * SEQ) / 128, 3), blk>>>(pb, DIM, DIM, DIM, DIM);

    // 2) all 16 QEr GEMMs in one launch (M=2048, N=1024, K=64 each)
    gemm128_qer<<<dim3(1024 / 128, SEQ / 128, NB * NH), blk>>>(qp, E, qer);

    // 3) fused attention
    attn_kernel<<<dim3(SEQ / 64, NH, NB), blk>>>(qp, kp, vp, mask, qer, attn);

    // 4) output projection -> d_out
    Batch3 ob;
    ob.A[0] = attn; ob.B[0] = Wo_w; ob.bias[0] = Wo_b; ob.C[0] = (float*)d_out;
    gemm128_batched<<<dim3(DIM / 128, (NB * SEQ) / 128, 1), blk>>>(ob, DIM, DIM, DIM, DIM);
}